// round 15
// baseline (speedup 1.0000x reference)
#include <cuda_runtime.h>
#include <cstdint>

#define Tn 2048
#define Hn 256
#define Bn 256
#define Pn 24

#define NT      512       // 16 warps: jhalf = wid&1, kslot = wid>>1
#define KSLOTS  8
#define KB_PER  32                       // k-rows per k-block
#define ITS_REG 20                       // first 20 k of each block in registers (fp32)
#define ITS_SM  (KB_PER - ITS_REG)       // last 12 k of each block in smem (int16)
#define WSM_ROWS (KSLOTS * ITS_SM)       // 96 rows in smem

// 2*log2(e): folded into W/b so tanh needs only EX2 (no pre-multiply)
#define SCALE   2.8853900817779268f
// int16 fixed-point: stored q = round(w_scaled * 2^15); decode folds 2^-15 into h.
#define QSCALE  32768.0f
#define QINV    3.0517578125e-05f        // 2^-15, exact

typedef unsigned long long ull;

// Shared memory layout (float offsets)
//  Wq  : [96][256] int16 rows (kslot*12+i) <-> k = kslot*32+20+i = 12288 floats (48 KB)
//  hb  : [2][256] batch-major hidden state, stored as h * 2^-15   =   512 floats ( 2 KB)
//  red : [16][256] (kslot*2 + b) partials (true scale)            =  4096 floats (16 KB)
//  xs  : [2][2048] cached x rows                                  =  4096 floats (16 KB)
#define OFF_W   0
#define OFF_H   12288
#define OFF_RED 12800
#define OFF_X   16896
#define SMEM_FLOATS 20992
#define SMEM_BYTES (SMEM_FLOATS * 4)

__device__ __forceinline__ void ffma2(ull& a, ull b, ull c) {
    asm("fma.rn.f32x2 %0, %1, %2, %0;" : "+l"(a) : "l"(b), "l"(c));
}
__device__ __forceinline__ ull packf2(float lo, float hi) {
    ull r; asm("mov.b64 %0, {%1, %2};" : "=l"(r) : "f"(lo), "f"(hi)); return r;
}
__device__ __forceinline__ ull dupf2(float v) {
    ull r; asm("mov.b64 %0, {%1, %1};" : "=l"(r) : "f"(v)); return r;
}
__device__ __forceinline__ float2 u2f(ull v) {
    float2 r; asm("mov.b64 {%0, %1}, %2;" : "=f"(r.x), "=f"(r.y) : "l"(v)); return r;
}
// Decode packed s16x2 -> f32x2 of the integer values (I2F.F32.S16 with half
// selectors; the 16-bit extraction is register-virtual, no extra SASS op).
__device__ __forceinline__ ull s16x2_to_f2(unsigned p) {
    float f0, f1;
    asm("{\n\t"
        ".reg .b16 lo, hi;\n\t"
        "mov.b32 {lo, hi}, %2;\n\t"
        "cvt.rn.f32.s16 %0, lo;\n\t"
        "cvt.rn.f32.s16 %1, hi;\n\t"
        "}" : "=f"(f0), "=f"(f1) : "r"(p));
    ull r; asm("mov.b64 %0, {%1, %2};" : "=l"(r) : "f"(f0), "f"(f1));
    return r;
}
// tanh with pre-scaled argument: input raw = 2*log2(e)*z; returns tanh(z).
// tanh(z) = 1 - 2/(2^raw + 1). EX2 + ADD + RCP + FFMA. Saturates correctly.
__device__ __forceinline__ float tanh_scaled(float raw) {
    float e, r;
    asm("ex2.approx.f32 %0, %1;" : "=f"(e) : "f"(raw));
    float ep1 = e + 1.0f;
    asm("rcp.approx.f32 %0, %1;" : "=f"(r) : "f"(ep1));
    return fmaf(-2.0f, r, 1.0f);
}

__global__ void __launch_bounds__(NT, 1)
rnn_persistent_kernel(const float* __restrict__ x,
                      const float* __restrict__ W_ih,
                      const float* __restrict__ W_hh,
                      const float* __restrict__ b_ih,
                      const float* __restrict__ b_hh,
                      const float* __restrict__ W_out,
                      const float* __restrict__ b_out,
                      float* __restrict__ out)
{
    extern __shared__ float sm[];
    short* Wq  = (short*)(sm + OFF_W);
    float* hb  = sm + OFF_H;
    float* red = sm + OFF_RED;
    float* xs  = sm + OFF_X;

    const int tid   = threadIdx.x;
    const int lane  = tid & 31;
    const int wid   = tid >> 5;
    const int jhalf = wid & 1;          // half of j-rows this warp covers
    const int kslot = wid >> 1;         // contiguous k-block [kslot*32, +32)
    const int kbase = kslot * KB_PER;
    const int j0    = jhalf * 128 + lane * 4;
    const int b0    = blockIdx.x * 2;
    const int fb    = tid >> 8;         // finalize: batch
    const int fj    = tid & 255;        // finalize: j row

    // ---------------- init ----------------
    for (int i = tid; i < Tn; i += NT) {
        xs[i]      = x[(size_t)b0 * Tn + i];
        xs[Tn + i] = x[(size_t)(b0 + 1) * Tn + i];
    }
    // smem W rows (int16): row r -> k = (r/ITS_SM)*32 + ITS_REG + (r%ITS_SM)
    // q = round(w * SCALE * 2^15), |w*SCALE| <= ~0.78 so no clamping in practice.
    for (int idx = tid; idx < 256 * (WSM_ROWS / 4); idx += NT) {
        int j  = idx / (WSM_ROWS / 4);
        int rc = idx % (WSM_ROWS / 4);
        #pragma unroll
        for (int q = 0; q < 4; ++q) {
            int r = rc * 4 + q;
            int k = (r / ITS_SM) * KB_PER + ITS_REG + (r % ITS_SM);
            int qi = __float2int_rn(W_hh[j * Hn + k] * SCALE * QSCALE);
            qi = max(-32767, min(32767, qi));
            Wq[r * 256 + j] = (short)qi;
        }
    }
    // register W: pre-scaled by SCALE * 2^15 (h carries the 2^-15), j-pairs.
    ull wr0[ITS_REG], wr1[ITS_REG];
    #pragma unroll
    for (int i = 0; i < ITS_REG; ++i) {
        int k = kbase + i;
        const float s = SCALE * QSCALE;
        wr0[i] = packf2(W_hh[(j0 + 0) * Hn + k] * s, W_hh[(j0 + 1) * Hn + k] * s);
        wr1[i] = packf2(W_hh[(j0 + 2) * Hn + k] * s, W_hh[(j0 + 3) * Hn + k] * s);
    }
    const float c1 = W_ih[fj] * SCALE;
    const float c0 = (b_ih[fj] + b_hh[fj]) * SCALE;
    if (tid < 512) hb[tid] = 0.f;
    __syncthreads();

    // ---------------- recurrence ----------------
    for (int t = 0; t < Tn; ++t) {
        // Hoisted x-projection: overlaps with phase B, off the post-bar1 chain.
        const float xc = fmaf(xs[fb * Tn + t], c1, c0);

        ull a00 = 0, a01 = 0, a10 = 0, a11 = 0;    // a{jpair}{batch}, true scale
        const float4* h0p = (const float4*)(hb + kbase);
        const float4* h1p = (const float4*)(hb + 256 + kbase);
        const short*  wp  = Wq + (kslot * ITS_SM) * 256 + j0;

        // Register-W segment (fma-heavy) — contiguous so ptxas batches loads.
        auto do_reg = [&]() {
            #pragma unroll
            for (int blk = 0; blk < ITS_REG / 4; ++blk) {
                float4 hv0 = h0p[blk];                 // broadcast LDS.128 (h * 2^-15)
                float4 hv1 = h1p[blk];
                #pragma unroll
                for (int c = 0; c < 4; ++c) {
                    int i = blk * 4 + c;
                    ull d0 = dupf2(((const float*)&hv0)[c]);
                    ull d1 = dupf2(((const float*)&hv1)[c]);
                    ffma2(a00, wr0[i], d0);
                    ffma2(a01, wr0[i], d1);
                    ffma2(a10, wr1[i], d0);
                    ffma2(a11, wr1[i], d1);
                }
            }
        };
        // Smem-W segment (int16, crossbar-light): LDS.64 per row (half the wf of
        // fp32), decoded with 2 I2F pairs; the 2^-15 dequant rides in h.
        auto do_smem = [&]() {
            #pragma unroll
            for (int blk = 0; blk < ITS_SM / 4; ++blk) {
                float4 hv0 = h0p[ITS_REG / 4 + blk];
                float4 hv1 = h1p[ITS_REG / 4 + blk];
                #pragma unroll
                for (int c = 0; c < 4; ++c) {
                    int r = blk * 4 + c;
                    uint2 wv = *(const uint2*)(wp + r * 256);  // LDS.64, 4 s16
                    ull w01 = s16x2_to_f2(wv.x);
                    ull w23 = s16x2_to_f2(wv.y);
                    ull d0 = dupf2(((const float*)&hv0)[c]);
                    ull d1 = dupf2(((const float*)&hv1)[c]);
                    ffma2(a00, w01, d0);
                    ffma2(a01, w01, d1);
                    ffma2(a10, w23, d0);
                    ffma2(a11, w23, d1);
                }
            }
        };
        // Coarse desync (R7-validated): half the warps hit the crossbar first,
        // half the fma pipe first.
        if (jhalf == 0) { do_reg(); do_smem(); }
        else            { do_smem(); do_reg(); }

        // k-slot partials
        {
            float2 p00 = u2f(a00), p10 = u2f(a10);
            float2 p01 = u2f(a01), p11 = u2f(a11);
            *(float4*)&red[(kslot * 2 + 0) * 256 + j0] = make_float4(p00.x, p00.y, p10.x, p10.y);
            *(float4*)&red[(kslot * 2 + 1) * 256 + j0] = make_float4(p01.x, p01.y, p11.x, p11.y);
        }
        __syncthreads();

        // finalize: thread (fb, fj) reduces its 8 k-slot partials (two chains).
        {
            float s0 = red[(0 * 2 + fb) * 256 + fj];
            float s1 = red[(1 * 2 + fb) * 256 + fj];
            s0 += red[(2 * 2 + fb) * 256 + fj];
            s1 += red[(3 * 2 + fb) * 256 + fj];
            s0 += red[(4 * 2 + fb) * 256 + fj];
            s1 += red[(5 * 2 + fb) * 256 + fj];
            s0 += red[(6 * 2 + fb) * 256 + fj];
            s1 += red[(7 * 2 + fb) * 256 + fj];
            float h = tanh_scaled(xc + (s0 + s1));
            hb[fb * 256 + fj] = h * QINV;   // store h * 2^-15 (exact scale)
        }
        __syncthreads();
    }

    // ---------------- output head (hb holds h_T * 2^-15) ----------------
    if (tid < 2 * Pn) {
        int b = tid / Pn;
        int p = tid % Pn;
        float s = b_out[p];
        const float* wrow = &W_out[p * Hn];
        const float* hrow = &hb[b * 256];
        #pragma unroll 8
        for (int h = 0; h < Hn; ++h)
            s = fmaf(hrow[h] * QSCALE, wrow[h], s);
        out[(size_t)(b0 + b) * Pn + p] = s;
    }
}

extern "C" void kernel_launch(void* const* d_in, const int* in_sizes, int n_in,
                              void* d_out, int out_size) {
    const float* x     = (const float*)d_in[0];
    const float* W_ih  = (const float*)d_in[1];
    const float* W_hh  = (const float*)d_in[2];
    const float* b_ih  = (const float*)d_in[3];
    const float* b_hh  = (const float*)d_in[4];
    const float* W_out = (const float*)d_in[5];
    const float* b_out = (const float*)d_in[6];
    float* out = (float*)d_out;

    cudaFuncSetAttribute(rnn_persistent_kernel,
                         cudaFuncAttributeMaxDynamicSharedMemorySize, SMEM_BYTES);
    rnn_persistent_kernel<<<Bn / 2, NT, SMEM_BYTES>>>(
        x, W_ih, W_hh, b_ih, b_hh, W_out, b_out, out);
}

// round 16
// speedup vs baseline: 1.2047x; 1.2047x over previous
#include <cuda_runtime.h>
#include <cstdint>

#define Tn 2048
#define Hn 256
#define Bn 256
#define Pn 24

#define NT      512       // 16 warps: jhalf = wid&1, kslot = wid>>1
#define KSLOTS  8
#define KB_PER  32                       // k-rows per k-block
#define ITS_REG 20                       // first 20 k of each block in registers (fp32)
#define ITS_SM  (KB_PER - ITS_REG)       // last 12 k of each block in smem (int16)
#define WSM_ROWS (KSLOTS * ITS_SM)       // 96 rows in smem

// 2*log2(e): folded into W/b so tanh needs only EX2 (no pre-multiply)
#define SCALE   2.8853900817779268f
// int16 fixed-point: stored offset-binary q' = q + 32768; decode via PRMT into
// float bits 0x4B000000|q' (= 2^23 + q'), then exact f32x2 subtract of C.
#define QSCALE  32768.0f
#define QINV    3.0517578125e-05f        // 2^-15, exact
#define OFFC    8421376.0f               // 2^23 + 32768, exact in fp32

typedef unsigned long long ull;

// Shared memory layout (float offsets)
//  Wq  : [96][256] u16 offset-binary rows                         = 12288 floats (48 KB)
//  hb  : [2][256] batch-major hidden state, stored as h * 2^-15   =   512 floats ( 2 KB)
//  red : [16][256] (kslot*2 + b) partials (true scale)            =  4096 floats (16 KB)
//  xs  : [2][2048] cached x rows                                  =  4096 floats (16 KB)
#define OFF_W   0
#define OFF_H   12288
#define OFF_RED 12800
#define OFF_X   16896
#define SMEM_FLOATS 20992
#define SMEM_BYTES (SMEM_FLOATS * 4)

__device__ __forceinline__ void ffma2(ull& a, ull b, ull c) {
    asm("fma.rn.f32x2 %0, %1, %2, %0;" : "+l"(a) : "l"(b), "l"(c));
}
__device__ __forceinline__ ull packf2(float lo, float hi) {
    ull r; asm("mov.b64 %0, {%1, %2};" : "=l"(r) : "f"(lo), "f"(hi)); return r;
}
__device__ __forceinline__ ull dupf2(float v) {
    ull r; asm("mov.b64 %0, {%1, %1};" : "=l"(r) : "f"(v)); return r;
}
__device__ __forceinline__ float2 u2f(ull v) {
    float2 r; asm("mov.b64 {%0, %1}, %2;" : "=f"(r.x), "=f"(r.y) : "l"(v)); return r;
}
// Decode packed offset-binary u16x2 -> f32x2 of the signed integer values.
// PRMT assembles {b0,b1,0x00,0x4B} and {b2,b3,0x00,0x4B} (float = 2^23 + q'),
// one f32x2 add subtracts C from both halves (exact: integer diff < 2^24).
// 2 PRMT on the idle alu pipe + 1 ADD2 on fma; no slow I2F.
__device__ __forceinline__ ull u16x2_to_f2(unsigned p, ull negC2) {
    ull r;
    asm("{\n\t"
        ".reg .b32 lo, hi;\n\t"
        "prmt.b32 lo, %1, 0x4B000000, 0x7410;\n\t"
        "prmt.b32 hi, %1, 0x4B000000, 0x7432;\n\t"
        "mov.b64 %0, {lo, hi};\n\t"
        "add.rn.f32x2 %0, %0, %2;\n\t"
        "}" : "=l"(r) : "r"(p), "l"(negC2));
    return r;
}
// tanh with pre-scaled argument: input raw = 2*log2(e)*z; returns tanh(z).
// tanh(z) = 1 - 2/(2^raw + 1). EX2 + ADD + RCP + FFMA. Saturates correctly.
__device__ __forceinline__ float tanh_scaled(float raw) {
    float e, r;
    asm("ex2.approx.f32 %0, %1;" : "=f"(e) : "f"(raw));
    float ep1 = e + 1.0f;
    asm("rcp.approx.f32 %0, %1;" : "=f"(r) : "f"(ep1));
    return fmaf(-2.0f, r, 1.0f);
}

__global__ void __launch_bounds__(NT, 1)
rnn_persistent_kernel(const float* __restrict__ x,
                      const float* __restrict__ W_ih,
                      const float* __restrict__ W_hh,
                      const float* __restrict__ b_ih,
                      const float* __restrict__ b_hh,
                      const float* __restrict__ W_out,
                      const float* __restrict__ b_out,
                      float* __restrict__ out)
{
    extern __shared__ float sm[];
    unsigned short* Wq = (unsigned short*)(sm + OFF_W);
    float* hb  = sm + OFF_H;
    float* red = sm + OFF_RED;
    float* xs  = sm + OFF_X;

    const int tid   = threadIdx.x;
    const int lane  = tid & 31;
    const int wid   = tid >> 5;
    const int jhalf = wid & 1;          // half of j-rows this warp covers
    const int kslot = wid >> 1;         // contiguous k-block [kslot*32, +32)
    const int kbase = kslot * KB_PER;
    const int j0    = jhalf * 128 + lane * 4;
    const int b0    = blockIdx.x * 2;
    const int fb    = tid >> 8;         // finalize: batch
    const int fj    = tid & 255;        // finalize: j row

    // ---------------- init ----------------
    for (int i = tid; i < Tn; i += NT) {
        xs[i]      = x[(size_t)b0 * Tn + i];
        xs[Tn + i] = x[(size_t)(b0 + 1) * Tn + i];
    }
    // smem W rows (offset-binary u16): row r -> k = (r/ITS_SM)*32 + ITS_REG + (r%ITS_SM)
    for (int idx = tid; idx < 256 * (WSM_ROWS / 4); idx += NT) {
        int j  = idx / (WSM_ROWS / 4);
        int rc = idx % (WSM_ROWS / 4);
        #pragma unroll
        for (int q = 0; q < 4; ++q) {
            int r = rc * 4 + q;
            int k = (r / ITS_SM) * KB_PER + ITS_REG + (r % ITS_SM);
            int qi = __float2int_rn(W_hh[j * Hn + k] * SCALE * QSCALE);
            qi = max(-32767, min(32767, qi));
            Wq[r * 256 + j] = (unsigned short)(qi + 32768);
        }
    }
    // register W: pre-scaled by SCALE * 2^15 (h carries the 2^-15), j-pairs.
    ull wr0[ITS_REG], wr1[ITS_REG];
    #pragma unroll
    for (int i = 0; i < ITS_REG; ++i) {
        int k = kbase + i;
        const float s = SCALE * QSCALE;
        wr0[i] = packf2(W_hh[(j0 + 0) * Hn + k] * s, W_hh[(j0 + 1) * Hn + k] * s);
        wr1[i] = packf2(W_hh[(j0 + 2) * Hn + k] * s, W_hh[(j0 + 3) * Hn + k] * s);
    }
    const float c1 = W_ih[fj] * SCALE;
    const float c0 = (b_ih[fj] + b_hh[fj]) * SCALE;
    const ull negC2 = dupf2(-OFFC);
    if (tid < 512) hb[tid] = 0.f;
    __syncthreads();

    // ---------------- recurrence ----------------
    for (int t = 0; t < Tn; ++t) {
        // Hoisted x-projection: overlaps with phase B, off the post-bar1 chain.
        const float xc = fmaf(xs[fb * Tn + t], c1, c0);

        ull a00 = 0, a01 = 0, a10 = 0, a11 = 0;    // a{jpair}{batch}, true scale
        const float4* h0p = (const float4*)(hb + kbase);
        const float4* h1p = (const float4*)(hb + 256 + kbase);
        const unsigned short* wp = Wq + (kslot * ITS_SM) * 256 + j0;

        // Register-W segment (fma-heavy) — contiguous so ptxas batches loads.
        auto do_reg = [&]() {
            #pragma unroll
            for (int blk = 0; blk < ITS_REG / 4; ++blk) {
                float4 hv0 = h0p[blk];                 // broadcast LDS.128 (h * 2^-15)
                float4 hv1 = h1p[blk];
                #pragma unroll
                for (int c = 0; c < 4; ++c) {
                    int i = blk * 4 + c;
                    ull d0 = dupf2(((const float*)&hv0)[c]);
                    ull d1 = dupf2(((const float*)&hv1)[c]);
                    ffma2(a00, wr0[i], d0);
                    ffma2(a01, wr0[i], d1);
                    ffma2(a10, wr1[i], d0);
                    ffma2(a11, wr1[i], d1);
                }
            }
        };
        // Smem-W segment (int16, crossbar-light): LDS.64 per row (half the wf
        // of fp32), decoded with PRMT + exact f32x2 offset-subtract.
        auto do_smem = [&]() {
            #pragma unroll
            for (int blk = 0; blk < ITS_SM / 4; ++blk) {
                float4 hv0 = h0p[ITS_REG / 4 + blk];
                float4 hv1 = h1p[ITS_REG / 4 + blk];
                #pragma unroll
                for (int c = 0; c < 4; ++c) {
                    int r = blk * 4 + c;
                    uint2 wv = *(const uint2*)(wp + r * 256);  // LDS.64, 4 u16
                    ull w01 = u16x2_to_f2(wv.x, negC2);
                    ull w23 = u16x2_to_f2(wv.y, negC2);
                    ull d0 = dupf2(((const float*)&hv0)[c]);
                    ull d1 = dupf2(((const float*)&hv1)[c]);
                    ffma2(a00, w01, d0);
                    ffma2(a01, w01, d1);
                    ffma2(a10, w23, d0);
                    ffma2(a11, w23, d1);
                }
            }
        };
        // Coarse desync (R7-validated): half the warps hit the crossbar first,
        // half the fma pipe first.
        if (jhalf == 0) { do_reg(); do_smem(); }
        else            { do_smem(); do_reg(); }

        // k-slot partials
        {
            float2 p00 = u2f(a00), p10 = u2f(a10);
            float2 p01 = u2f(a01), p11 = u2f(a11);
            *(float4*)&red[(kslot * 2 + 0) * 256 + j0] = make_float4(p00.x, p00.y, p10.x, p10.y);
            *(float4*)&red[(kslot * 2 + 1) * 256 + j0] = make_float4(p01.x, p01.y, p11.x, p11.y);
        }
        __syncthreads();

        // finalize: thread (fb, fj) reduces its 8 k-slot partials (two chains).
        {
            float s0 = red[(0 * 2 + fb) * 256 + fj];
            float s1 = red[(1 * 2 + fb) * 256 + fj];
            s0 += red[(2 * 2 + fb) * 256 + fj];
            s1 += red[(3 * 2 + fb) * 256 + fj];
            s0 += red[(4 * 2 + fb) * 256 + fj];
            s1 += red[(5 * 2 + fb) * 256 + fj];
            s0 += red[(6 * 2 + fb) * 256 + fj];
            s1 += red[(7 * 2 + fb) * 256 + fj];
            float h = tanh_scaled(xc + (s0 + s1));
            hb[fb * 256 + fj] = h * QINV;   // store h * 2^-15 (exact scale)
        }
        __syncthreads();
    }

    // ---------------- output head (hb holds h_T * 2^-15) ----------------
    if (tid < 2 * Pn) {
        int b = tid / Pn;
        int p = tid % Pn;
        float s = b_out[p];
        const float* wrow = &W_out[p * Hn];
        const float* hrow = &hb[b * 256];
        #pragma unroll 8
        for (int h = 0; h < Hn; ++h)
            s = fmaf(hrow[h] * QSCALE, wrow[h], s);
        out[(size_t)(b0 + b) * Pn + p] = s;
    }
}

extern "C" void kernel_launch(void* const* d_in, const int* in_sizes, int n_in,
                              void* d_out, int out_size) {
    const float* x     = (const float*)d_in[0];
    const float* W_ih  = (const float*)d_in[1];
    const float* W_hh  = (const float*)d_in[2];
    const float* b_ih  = (const float*)d_in[3];
    const float* b_hh  = (const float*)d_in[4];
    const float* W_out = (const float*)d_in[5];
    const float* b_out = (const float*)d_in[6];
    float* out = (float*)d_out;

    cudaFuncSetAttribute(rnn_persistent_kernel,
                         cudaFuncAttributeMaxDynamicSharedMemorySize, SMEM_BYTES);
    rnn_persistent_kernel<<<Bn / 2, NT, SMEM_BYTES>>>(
        x, W_ih, W_hh, b_ih, b_hh, W_out, b_out, out);
}